// round 14
// baseline (speedup 1.0000x reference)
#include <cuda_runtime.h>
#include <cuda_bf16.h>
#include <math.h>
#include <stdint.h>

#define BB 8192
#define DV 1024
#define DT 768
#define LD_X 1797
#define HH 256
#define CC 5
#define GHH 128
#define KNN 8
#define FDIM 512
#define GI 773
#define NIMG 512
#define NEGV (-1000000000.0f)

__device__ float g_xn[(size_t)BB * 1792];
__device__ float g_base[(size_t)BB * FDIM];
__device__ float g_cp[(size_t)BB * CC];
__device__ float g_agg[(size_t)BB * FDIM];
__device__ float g_t1[(size_t)BB * HH];
__device__ float g_tok[(size_t)BB * HH];
__device__ float g_hid[(size_t)BB * GHH];
__device__ float g_gp[(size_t)BB * 2];
__device__ float g_ent[BB];
__device__ float g_fused[(size_t)BB * FDIM];
__device__ float g_u1[(size_t)BB * FDIM];
__device__ float g_h[(size_t)BB * HH];
__device__ float g_w[(size_t)BB * KNN];
__device__ int   g_nidx[(size_t)BB * KNN];
__device__ int   g_cnt[NIMG];
__device__ int   g_off[NIMG + 1];
__device__ int   g_cur[NIMG];
__device__ int   g_bucket[BB];

#define WSZ 1413120
__device__ __align__(16) __nv_bfloat16 g_whi[WSZ];
__device__ __align__(16) __nv_bfloat16 g_wlo[WSZ];
#define OW_V   0
#define OW_T   262144
#define OW_C1  458752
#define OW_C2  589824
#define OW_G1  655360
#define OW_U1  757760
#define OW_U2  1019904
#define OW_CL1 1282048

__device__ __forceinline__ uint32_t smem_u32(const void* p) {
    uint32_t a;
    asm("{ .reg .u64 t; cvta.to.shared.u64 t, %1; cvt.u32.u64 %0, t; }" : "=r"(a) : "l"(p));
    return a;
}
__device__ __forceinline__ void ldm_x4(uint32_t& r0, uint32_t& r1, uint32_t& r2, uint32_t& r3,
                                       uint32_t addr) {
    asm volatile("ldmatrix.sync.aligned.m8n8.x4.shared.b16 {%0,%1,%2,%3}, [%4];"
        : "=r"(r0), "=r"(r1), "=r"(r2), "=r"(r3) : "r"(addr));
}
__device__ __forceinline__ void mma16816(float* d, const uint32_t* a, uint32_t b0, uint32_t b1) {
    asm volatile(
        "mma.sync.aligned.m16n8k16.row.col.f32.bf16.bf16.f32 "
        "{%0,%1,%2,%3}, {%4,%5,%6,%7}, {%8,%9}, {%0,%1,%2,%3};"
        : "+f"(d[0]), "+f"(d[1]), "+f"(d[2]), "+f"(d[3])
        : "r"(a[0]), "r"(a[1]), "r"(a[2]), "r"(a[3]), "r"(b0), "r"(b1));
}
__device__ __forceinline__ void split2(float x, float y, uint32_t& hi, uint32_t& lo) {
    __nv_bfloat162 h = __floats2bfloat162_rn(x, y);
    float xr = x - __bfloat162float(__low2bfloat16(h));
    float yr = y - __bfloat162float(__high2bfloat16(h));
    __nv_bfloat162 l = __floats2bfloat162_rn(xr, yr);
    hi = *(uint32_t*)&h;
    lo = *(uint32_t*)&l;
}

struct WJob { const float* W; __nv_bfloat16* hi; __nv_bfloat16* lo; int K, N, K2, tile0, tilesK; };
struct WJobs { WJob j[8]; };

__global__ void wsplit_all(WJobs jobs)
{
    __shared__ float tile[32][33];
    int b = blockIdx.x;
    int ji = 0;
    #pragma unroll
    for (int i = 1; i < 8; i++) if (b >= jobs.j[i].tile0) ji = i;
    WJob jb = jobs.j[ji];
    int t = b - jb.tile0;
    int kt = (t % jb.tilesK) * 32, nt = (t / jb.tilesK) * 32;
    int tx = threadIdx.x, ty = threadIdx.y;
    #pragma unroll
    for (int i = 0; i < 4; i++) {
        int k = kt + ty + i * 8;
        tile[ty + i * 8][tx] = (k < jb.K) ? jb.W[(size_t)k * jb.N + nt + tx] : 0.f;
    }
    __syncthreads();
    #pragma unroll
    for (int i = 0; i < 4; i++) {
        int n = nt + ty + i * 8;
        int k = kt + tx;
        float v = tile[tx][ty + i * 8];
        __nv_bfloat16 h = __float2bfloat16_rn(v);
        __nv_bfloat16 l = __float2bfloat16_rn(v - __bfloat162float(h));
        jb.hi[(size_t)n * jb.K2 + k] = h;
        jb.lo[(size_t)n * jb.K2 + k] = l;
    }
}

__global__ void ln_kernel(const float* __restrict__ x,
                          const float* __restrict__ gv, const float* __restrict__ bv,
                          const float* __restrict__ gt, const float* __restrict__ bt)
{
    int row = blockIdx.x;
    const float* xr = x + (size_t)row * LD_X;
    float* outr = g_xn + (size_t)row * 1792;
    __shared__ float red[256];
    int tid = threadIdx.x;

    float s = 0.f;
    for (int c = tid; c < DV; c += 256) s += xr[c];
    red[tid] = s; __syncthreads();
    for (int o = 128; o > 0; o >>= 1) { if (tid < o) red[tid] += red[tid + o]; __syncthreads(); }
    float m = red[0] / (float)DV;
    __syncthreads();
    float s2 = 0.f;
    for (int c = tid; c < DV; c += 256) { float d = xr[c] - m; s2 += d * d; }
    red[tid] = s2; __syncthreads();
    for (int o = 128; o > 0; o >>= 1) { if (tid < o) red[tid] += red[tid + o]; __syncthreads(); }
    float r = rsqrtf(red[0] / (float)DV + 1e-5f);
    __syncthreads();
    for (int c = tid; c < DV; c += 256) outr[c] = (xr[c] - m) * r * gv[c] + bv[c];

    s = 0.f;
    for (int c = tid; c < DT; c += 256) s += xr[DV + c];
    red[tid] = s; __syncthreads();
    for (int o = 128; o > 0; o >>= 1) { if (tid < o) red[tid] += red[tid + o]; __syncthreads(); }
    m = red[0] / (float)DT;
    __syncthreads();
    s2 = 0.f;
    for (int c = tid; c < DT; c += 256) { float d = xr[DV + c] - m; s2 += d * d; }
    red[tid] = s2; __syncthreads();
    for (int o = 128; o > 0; o >>= 1) { if (tid < o) red[tid] += red[tid + o]; __syncthreads(); }
    r = rsqrtf(red[0] / (float)DT + 1e-5f);
    __syncthreads();
    for (int c = tid; c < DT; c += 256) outr[DV + c] = (xr[DV + c] - m) * r * gt[c] + bt[c];
}

#define E_BIAS  0
#define E_RELU  1
#define E_RESID 2
#define E_BN    3
#define SRW 20
#define BUFW (128*SRW)
#define GEMM_DSMEM (8 * BUFW * 4)

template<int ASRC>
__device__ __forceinline__ float loadA(const float* __restrict__ A, int lda, int m, int kk, int K)
{
    if (ASRC == 0) return (kk < K) ? A[(size_t)m * lda + kk] : 0.f;
    if (kk < FDIM)      return g_base[(size_t)m * FDIM + kk];
    if (kk < FDIM + CC) return g_cp[(size_t)m * CC + (kk - FDIM)];
    if (kk < GI)        return g_tok[(size_t)m * HH + (kk - FDIM - CC)];
    return 0.f;
}

// 512 threads, 16 warps as 4m x 4n; warp tile 32x32; CTA tile 128x128.
template<int EPI, int ASRC>
__global__ void __launch_bounds__(512)
gemm_mma(const float* __restrict__ A, int lda,
         const __nv_bfloat16* __restrict__ Whi,
         const __nv_bfloat16* __restrict__ Wlo,
         int K2,
         const float* __restrict__ bias,
         float* __restrict__ C, int ldc,
         int N, int K,
         const float* __restrict__ scale, const float* __restrict__ shift,
         const float* __restrict__ resid, int ldr, float alpha,
         const float* __restrict__ gpp)
{
    extern __shared__ uint32_t dsm[];
    uint32_t* sAhi = dsm;
    uint32_t* sAlo = dsm + 2 * BUFW;
    uint32_t* sBhi = dsm + 4 * BUFW;
    uint32_t* sBlo = dsm + 6 * BUFW;
    uint32_t pbase = smem_u32(dsm);

    int tid = threadIdx.x;
    int lane = tid & 31, wid = tid >> 5;
    int bm = blockIdx.y * 128, bn = blockIdx.x * 128;
    int wm = (wid >> 2) * 32, wn = (wid & 3) * 32;

    float acc[2][4][4];
    #pragma unroll
    for (int mf = 0; mf < 2; mf++)
        #pragma unroll
        for (int nf = 0; nf < 4; nf++)
            #pragma unroll
            for (int q = 0; q < 4; q++) acc[mf][nf][q] = 0.f;

    int a_r = tid >> 2, a_kq = (tid & 3) * 8;
    int b_n = tid & 127, b_kb = (tid >> 7) * 8;

    float aReg[8];
    uint4 bh4, bl4;

    int nch = (K + 31) / 32;
    const bool avec = (ASRC == 0) && ((lda & 3) == 0) && ((K & 31) == 0);

    int aRow = wm + (lane & 7) + ((lane >> 3) & 1) * 8;
    int aKw  = ((lane >> 4) & 1) * 4;
    int bRow = wn + (lane & 7) + ((lane >> 4) & 1) * 8;
    int bKw  = ((lane >> 3) & 1) * 4;

    {
        if (avec) {
            *(float4*)&aReg[0] = *(const float4*)&A[(size_t)(bm + a_r) * lda + a_kq];
            *(float4*)&aReg[4] = *(const float4*)&A[(size_t)(bm + a_r) * lda + a_kq + 4];
        } else {
            #pragma unroll
            for (int q = 0; q < 8; q++)
                aReg[q] = loadA<ASRC>(A, lda, bm + a_r, a_kq + q, K);
        }
        bh4 = *(const uint4*)(Whi + (size_t)(bn + b_n) * K2 + b_kb);
        bl4 = *(const uint4*)(Wlo + (size_t)(bn + b_n) * K2 + b_kb);
    }

    for (int ch = 0; ch < nch; ch++) {
        int bo = (ch & 1) * BUFW;
        {
            uint32_t h[4], l[4];
            split2(aReg[0], aReg[1], h[0], l[0]);
            split2(aReg[2], aReg[3], h[1], l[1]);
            split2(aReg[4], aReg[5], h[2], l[2]);
            split2(aReg[6], aReg[7], h[3], l[3]);
            int idx = bo + a_r * SRW + (a_kq >> 1);
            *(uint4*)&sAhi[idx] = make_uint4(h[0], h[1], h[2], h[3]);
            *(uint4*)&sAlo[idx] = make_uint4(l[0], l[1], l[2], l[3]);
        }
        {
            int idx = bo + b_n * SRW + (b_kb >> 1);
            *(uint4*)&sBhi[idx] = bh4;
            *(uint4*)&sBlo[idx] = bl4;
        }
        __syncthreads();   // single barrier per chunk (double-buffered)

        if (ch + 1 < nch) {
            int k0 = (ch + 1) * 32;
            if (avec) {
                *(float4*)&aReg[0] = *(const float4*)&A[(size_t)(bm + a_r) * lda + k0 + a_kq];
                *(float4*)&aReg[4] = *(const float4*)&A[(size_t)(bm + a_r) * lda + k0 + a_kq + 4];
            } else {
                #pragma unroll
                for (int q = 0; q < 8; q++)
                    aReg[q] = loadA<ASRC>(A, lda, bm + a_r, k0 + a_kq + q, K);
            }
            bh4 = *(const uint4*)(Whi + (size_t)(bn + b_n) * K2 + k0 + b_kb);
            bl4 = *(const uint4*)(Wlo + (size_t)(bn + b_n) * K2 + k0 + b_kb);
        }

        uint32_t pA  = pbase + bo * 4;
        uint32_t pAl = pA + 2 * BUFW * 4;
        uint32_t pB  = pA + 4 * BUFW * 4;
        uint32_t pBl = pA + 6 * BUFW * 4;
        #pragma unroll
        for (int ks = 0; ks < 2; ks++) {
            uint32_t ah[2][4], al[2][4];
            #pragma unroll
            for (int mf = 0; mf < 2; mf++) {
                uint32_t off = (uint32_t)((aRow + mf * 16) * SRW + ks * 8 + aKw) * 4u;
                ldm_x4(ah[mf][0], ah[mf][1], ah[mf][2], ah[mf][3], pA + off);
                ldm_x4(al[mf][0], al[mf][1], al[mf][2], al[mf][3], pAl + off);
            }
            uint32_t bh[4][2], bl[4][2];
            #pragma unroll
            for (int np = 0; np < 2; np++) {
                uint32_t off = (uint32_t)((bRow + np * 16) * SRW + ks * 8 + bKw) * 4u;
                ldm_x4(bh[2 * np][0], bh[2 * np][1], bh[2 * np + 1][0], bh[2 * np + 1][1], pB + off);
                ldm_x4(bl[2 * np][0], bl[2 * np][1], bl[2 * np + 1][0], bl[2 * np + 1][1], pBl + off);
            }
            #pragma unroll
            for (int nf = 0; nf < 4; nf++) {
                #pragma unroll
                for (int mf = 0; mf < 2; mf++) {
                    mma16816(acc[mf][nf], ah[mf], bh[nf][0], bh[nf][1]);
                    mma16816(acc[mf][nf], ah[mf], bl[nf][0], bl[nf][1]);
                    mma16816(acc[mf][nf], al[mf], bh[nf][0], bh[nf][1]);
                }
            }
        }
        // no trailing barrier: next iteration writes the OTHER buffer
    }

    int mb = bm + wm + (lane >> 2);
    int nb = bn + wn + 2 * (lane & 3);
    #pragma unroll
    for (int mf = 0; mf < 2; mf++) {
        #pragma unroll
        for (int nf = 0; nf < 4; nf++) {
            int n0 = nb + nf * 8;
            #pragma unroll
            for (int half = 0; half < 2; half++) {
                int m = mb + mf * 16 + half * 8;
                float v0 = acc[mf][nf][half * 2 + 0] + bias[n0];
                float v1 = acc[mf][nf][half * 2 + 1] + bias[n0 + 1];
                if (EPI == E_RELU) { v0 = fmaxf(v0, 0.f); v1 = fmaxf(v1, 0.f); }
                else if (EPI == E_RESID) {
                    float g = gpp[(size_t)m * 2 + (n0 >= HH ? 1 : 0)];
                    v0 = resid[(size_t)m * ldr + n0] * g + alpha * v0;
                    v1 = resid[(size_t)m * ldr + n0 + 1] * g + alpha * v1;
                }
                else if (EPI == E_BN) {
                    float rs = rsqrtf(1.f + 1e-5f);
                    v0 = fmaxf(v0 * (scale[n0] * rs) + shift[n0], 0.f);
                    v1 = fmaxf(v1 * (scale[n0 + 1] * rs) + shift[n0 + 1], 0.f);
                }
                *(float2*)&C[(size_t)m * ldc + n0] = make_float2(v0, v1);
            }
        }
    }
}

__global__ void cp_kernel(const float* __restrict__ Wcp, const float* __restrict__ bcp)
{
    int warp = threadIdx.x >> 5, lane = threadIdx.x & 31;
    int row = blockIdx.x * 8 + warp;
    if (row >= BB) return;
    const float* f = g_base + (size_t)row * FDIM;
    float acc[CC] = {0, 0, 0, 0, 0};
    for (int k = lane; k < FDIM; k += 32) {
        float fv = f[k];
        #pragma unroll
        for (int c = 0; c < CC; c++) acc[c] += fv * Wcp[k * CC + c];
    }
    #pragma unroll
    for (int c = 0; c < CC; c++)
        for (int o = 16; o; o >>= 1) acc[c] += __shfl_xor_sync(0xffffffff, acc[c], o);
    if (lane == 0) {
        float z[CC], mx = -1e30f, sum = 0.f;
        #pragma unroll
        for (int c = 0; c < CC; c++) { z[c] = acc[c] + bcp[c]; mx = fmaxf(mx, z[c]); }
        #pragma unroll
        for (int c = 0; c < CC; c++) { z[c] = expf(z[c] - mx); sum += z[c]; }
        #pragma unroll
        for (int c = 0; c < CC; c++) g_cp[(size_t)row * CC + c] = z[c] / sum;
    }
}

__global__ void zero_cnt_kernel() {
    int t = blockIdx.x * blockDim.x + threadIdx.x;
    if (t < NIMG) { g_cnt[t] = 0; g_cur[t] = 0; }
}
__global__ void count_kernel(const float* __restrict__ x) {
    int i = blockIdx.x * blockDim.x + threadIdx.x;
    if (i >= BB) return;
    int im = (int)x[(size_t)i * LD_X + 1796];
    atomicAdd(&g_cnt[im], 1);
}
__global__ void prefix_kernel() {
    if (blockIdx.x == 0 && threadIdx.x == 0) {
        int s = 0;
        for (int i = 0; i < NIMG; i++) { g_off[i] = s; s += g_cnt[i]; }
        g_off[NIMG] = s;
    }
}
__global__ void fill_kernel(const float* __restrict__ x) {
    int i = blockIdx.x * blockDim.x + threadIdx.x;
    if (i >= BB) return;
    int im = (int)x[(size_t)i * LD_X + 1796];
    int p = atomicAdd(&g_cur[im], 1);
    g_bucket[g_off[im] + p] = i;
}

__device__ __forceinline__ void topk_insert(float* val, int* ind, float s, int j) {
    if (s > val[KNN - 1]) {
        int p = KNN - 1;
        while (p > 0 && s > val[p - 1]) { val[p] = val[p - 1]; ind[p] = ind[p - 1]; p--; }
        val[p] = s; ind[p] = j;
    }
}

__global__ void knn_topk_kernel(const float* __restrict__ x)
{
    int i = blockIdx.x * blockDim.x + threadIdx.x;
    if (i >= BB) return;
    const float* xi = x + (size_t)i * LD_X;
    float cx = xi[1792], cy = xi[1793];
    int im = (int)xi[1796];
    float sqi = cx * cx + cy * cy;

    float val[KNN]; int ind[KNN];
    #pragma unroll
    for (int k = 0; k < KNN; k++) { val[k] = NEGV; ind[k] = 0; }

    int s = g_off[im], e = g_off[im + 1];
    int m = 0;
    for (int p = s; p < e; p++) {
        int j = g_bucket[p];
        if (j == i) continue;
        const float* xj = x + (size_t)j * LD_X;
        float jx = xj[1792], jy = xj[1793];
        float sqj = jx * jx + jy * jy;
        float d2 = sqi + sqj - 2.f * (cx * jx + cy * jy);
        float sim = -sqrtf(fmaxf(d2, 0.f));
        m++;
        topk_insert(val, ind, sim, j);
    }
    if (m == 0) {
        for (int j = 0; j < BB; j++) {
            if (j == i) continue;
            const float* xj = x + (size_t)j * LD_X;
            float jx = xj[1792], jy = xj[1793];
            float sqj = jx * jx + jy * jy;
            float d2 = sqi + sqj - 2.f * (cx * jx + cy * jy);
            float sim = -sqrtf(fmaxf(d2, 0.f));
            topk_insert(val, ind, sim, j);
        }
    }
    float mx = val[0];
    float w[KNN], sum = 0.f;
    #pragma unroll
    for (int k = 0; k < KNN; k++) { w[k] = expf(val[k] - mx); sum += w[k]; }
    float inv = 1.f / sum;
    #pragma unroll
    for (int k = 0; k < KNN; k++) {
        g_w[(size_t)i * KNN + k] = w[k] * inv;
        g_nidx[(size_t)i * KNN + k] = ind[k];
    }
}

__global__ void gather_kernel(const float* __restrict__ F, float* __restrict__ out,
                              const float* __restrict__ gp, int gated)
{
    int row = blockIdx.x;
    __shared__ float sw0[KNN], sw1[KNN];
    __shared__ int   si[KNN];
    if (threadIdx.x < KNN) {
        int k = threadIdx.x;
        float w = g_w[(size_t)row * KNN + k];
        int j = g_nidx[(size_t)row * KNN + k];
        si[k] = j;
        if (gated) { sw0[k] = w * gp[(size_t)j * 2]; sw1[k] = w * gp[(size_t)j * 2 + 1]; }
        else       { sw0[k] = w; sw1[k] = w; }
    }
    __syncthreads();
    for (int c = threadIdx.x; c < FDIM; c += blockDim.x) {
        const float* s = (c < HH) ? sw0 : sw1;
        float acc = 0.f;
        #pragma unroll
        for (int k = 0; k < KNN; k++) acc += s[k] * F[(size_t)si[k] * FDIM + c];
        out[(size_t)row * FDIM + c] = acc;
    }
}

__global__ void gate2_kernel(const float* __restrict__ Wg2, const float* __restrict__ bg2)
{
    int warp = threadIdx.x >> 5, lane = threadIdx.x & 31;
    int row = blockIdx.x * 8 + warp;
    if (row >= BB) return;
    float a0 = 0.f, a1 = 0.f;
    const float* h = g_hid + (size_t)row * GHH;
    for (int k = lane; k < GHH; k += 32) {
        float hv = h[k];
        a0 += hv * Wg2[k * 2];
        a1 += hv * Wg2[k * 2 + 1];
    }
    for (int o = 16; o; o >>= 1) {
        a0 += __shfl_xor_sync(0xffffffff, a0, o);
        a1 += __shfl_xor_sync(0xffffffff, a1, o);
    }
    if (lane == 0) {
        float z0 = a0 + bg2[0], z1 = a1 + bg2[1];
        float mx = fmaxf(z0, z1);
        float e0 = expf(z0 - mx), e1 = expf(z1 - mx);
        float sinv = 1.f / (e0 + e1);
        float p0 = e0 * sinv, p1 = e1 * sinv;
        g_gp[(size_t)row * 2] = p0;
        g_gp[(size_t)row * 2 + 1] = p1;
        g_ent[row] = -(p0 * logf(p0 + 1e-8f) + p1 * logf(p1 + 1e-8f));
    }
}

__global__ void c2_kernel(const float* __restrict__ Wc2, const float* __restrict__ bc2,
                          float* __restrict__ out)
{
    int warp = threadIdx.x >> 5, lane = threadIdx.x & 31;
    int row = blockIdx.x * 8 + warp;
    if (row >= BB) return;
    const float* h = g_h + (size_t)row * HH;
    float acc[CC] = {0, 0, 0, 0, 0};
    for (int k = lane; k < HH; k += 32) {
        float hv = h[k];
        #pragma unroll
        for (int c = 0; c < CC; c++) acc[c] += hv * Wc2[k * CC + c];
    }
    #pragma unroll
    for (int c = 0; c < CC; c++)
        for (int o = 16; o; o >>= 1) acc[c] += __shfl_xor_sync(0xffffffff, acc[c], o);
    if (lane == 0) {
        #pragma unroll
        for (int c = 0; c < CC; c++) out[(size_t)row * CC + c] = acc[c] + bc2[c];
    }
}

__global__ void ent_reduce_kernel(float* __restrict__ out)
{
    __shared__ float red[256];
    int tid = threadIdx.x;
    float s = 0.f;
    for (int t = tid; t < BB; t += 256) s += g_ent[t];
    red[tid] = s; __syncthreads();
    for (int o = 128; o > 0; o >>= 1) { if (tid < o) red[tid] += red[tid + o]; __syncthreads(); }
    if (tid == 0) out[0] = red[0] / (float)BB * 0.01f;
}

static float* sym_f(const void* p) { return (float*)p; }

extern "C" void kernel_launch(void* const* d_in, const int* in_sizes, int n_in,
                              void* d_out, int out_size)
{
    const float* x     = (const float*)d_in[0];
    const float* ln_vg = (const float*)d_in[1];
    const float* ln_vb = (const float*)d_in[2];
    const float* ln_tg = (const float*)d_in[3];
    const float* ln_tb = (const float*)d_in[4];
    const float* W_v   = (const float*)d_in[5];
    const float* b_v   = (const float*)d_in[6];
    const float* W_t   = (const float*)d_in[7];
    const float* b_t   = (const float*)d_in[8];
    const float* W_cp  = (const float*)d_in[9];
    const float* b_cp  = (const float*)d_in[10];
    const float* W_ctx1 = (const float*)d_in[11];
    const float* b_ctx1 = (const float*)d_in[12];
    const float* W_ctx2 = (const float*)d_in[13];
    const float* b_ctx2 = (const float*)d_in[14];
    const float* W_g1  = (const float*)d_in[15];
    const float* b_g1  = (const float*)d_in[16];
    const float* W_g2  = (const float*)d_in[17];
    const float* b_g2  = (const float*)d_in[18];
    const float* W_gu1 = (const float*)d_in[19];
    const float* b_gu1 = (const float*)d_in[20];
    const float* W_gu2 = (const float*)d_in[21];
    const float* b_gu2 = (const float*)d_in[22];
    const float* W_c1  = (const float*)d_in[23];
    const float* b_c1  = (const float*)d_in[24];
    const float* bn_g  = (const float*)d_in[25];
    const float* bn_b  = (const float*)d_in[26];
    const float* W_c2  = (const float*)d_in[27];
    const float* b_c2  = (const float*)d_in[28];
    float* out = (float*)d_out;

    void *p_xn, *p_base, *p_agg, *p_t1, *p_tok, *p_hid, *p_fused, *p_u1, *p_h, *p_gp;
    void *p_whi, *p_wlo;
    cudaGetSymbolAddress(&p_xn, g_xn);
    cudaGetSymbolAddress(&p_base, g_base);
    cudaGetSymbolAddress(&p_agg, g_agg);
    cudaGetSymbolAddress(&p_t1, g_t1);
    cudaGetSymbolAddress(&p_tok, g_tok);
    cudaGetSymbolAddress(&p_hid, g_hid);
    cudaGetSymbolAddress(&p_fused, g_fused);
    cudaGetSymbolAddress(&p_u1, g_u1);
    cudaGetSymbolAddress(&p_h, g_h);
    cudaGetSymbolAddress(&p_gp, g_gp);
    cudaGetSymbolAddress(&p_whi, g_whi);
    cudaGetSymbolAddress(&p_wlo, g_wlo);
    float* xn    = sym_f(p_xn);
    float* base  = sym_f(p_base);
    float* agg   = sym_f(p_agg);
    float* t1    = sym_f(p_t1);
    float* tok   = sym_f(p_tok);
    float* hid   = sym_f(p_hid);
    float* fused = sym_f(p_fused);
    float* u1    = sym_f(p_u1);
    float* hbuf  = sym_f(p_h);
    float* gp    = sym_f(p_gp);
    __nv_bfloat16* whi = (__nv_bfloat16*)p_whi;
    __nv_bfloat16* wlo = (__nv_bfloat16*)p_wlo;

    cudaFuncSetAttribute(gemm_mma<E_BIAS, 0>,  cudaFuncAttributeMaxDynamicSharedMemorySize, GEMM_DSMEM);
    cudaFuncSetAttribute(gemm_mma<E_RELU, 0>,  cudaFuncAttributeMaxDynamicSharedMemorySize, GEMM_DSMEM);
    cudaFuncSetAttribute(gemm_mma<E_RELU, 1>,  cudaFuncAttributeMaxDynamicSharedMemorySize, GEMM_DSMEM);
    cudaFuncSetAttribute(gemm_mma<E_RESID, 0>, cudaFuncAttributeMaxDynamicSharedMemorySize, GEMM_DSMEM);
    cudaFuncSetAttribute(gemm_mma<E_BN, 0>,    cudaFuncAttributeMaxDynamicSharedMemorySize, GEMM_DSMEM);

    WJobs jobs;
    int t0 = 0;
    auto setj = [&](int i, const float* W, int off, int K, int N, int K2) {
        jobs.j[i] = WJob{ W, whi + off, wlo + off, K, N, K2, t0, K2 / 32 };
        t0 += (K2 / 32) * (N / 32);
    };
    setj(0, W_v,    OW_V,   DV,   HH,   1024);
    setj(1, W_t,    OW_T,   DT,   HH,   768);
    setj(2, W_ctx1, OW_C1,  FDIM, HH,   512);
    setj(3, W_ctx2, OW_C2,  HH,   HH,   256);
    setj(4, W_g1,   OW_G1,  GI,   GHH,  800);
    setj(5, W_gu1,  OW_U1,  FDIM, FDIM, 512);
    setj(6, W_gu2,  OW_U2,  FDIM, FDIM, 512);
    setj(7, W_c1,   OW_CL1, FDIM, HH,   512);
    wsplit_all<<<t0, dim3(32, 8)>>>(jobs);

    ln_kernel<<<BB, 256>>>(x, ln_vg, ln_vb, ln_tg, ln_tb);

    dim3 gA(HH / 128, BB / 128);
    gemm_mma<E_BIAS, 0><<<gA, 512, GEMM_DSMEM>>>(xn, 1792, whi + OW_V, wlo + OW_V, 1024, b_v,
        base, FDIM, HH, DV, nullptr, nullptr, nullptr, 0, 0.f, nullptr);
    gemm_mma<E_BIAS, 0><<<gA, 512, GEMM_DSMEM>>>(xn + DV, 1792, whi + OW_T, wlo + OW_T, 768, b_t,
        base + HH, FDIM, HH, DT, nullptr, nullptr, nullptr, 0, 0.f, nullptr);

    cp_kernel<<<BB / 8, 256>>>(W_cp, b_cp);

    zero_cnt_kernel<<<2, 256>>>();
    count_kernel<<<BB / 256, 256>>>(x);
    prefix_kernel<<<1, 32>>>();
    fill_kernel<<<BB / 256, 256>>>(x);
    knn_topk_kernel<<<BB / 256, 256>>>(x);

    gather_kernel<<<BB, 128>>>(base, agg, nullptr, 0);
    gemm_mma<E_RELU, 0><<<gA, 512, GEMM_DSMEM>>>(agg, FDIM, whi + OW_C1, wlo + OW_C1, 512, b_ctx1,
        t1, HH, HH, FDIM, nullptr, nullptr, nullptr, 0, 0.f, nullptr);
    gemm_mma<E_BIAS, 0><<<gA, 512, GEMM_DSMEM>>>(t1, HH, whi + OW_C2, wlo + OW_C2, 256, b_ctx2,
        tok, HH, HH, HH, nullptr, nullptr, nullptr, 0, 0.f, nullptr);

    dim3 gG(GHH / 128, BB / 128);
    gemm_mma<E_RELU, 1><<<gG, 512, GEMM_DSMEM>>>(nullptr, 0, whi + OW_G1, wlo + OW_G1, 800, b_g1,
        hid, GHH, GHH, GI, nullptr, nullptr, nullptr, 0, 0.f, nullptr);
    gate2_kernel<<<BB / 8, 256>>>(W_g2, b_g2);

    gather_kernel<<<BB, 128>>>(base, agg, gp, 1);
    dim3 gF(FDIM / 128, BB / 128);
    gemm_mma<E_RELU, 0><<<gF, 512, GEMM_DSMEM>>>(agg, FDIM, whi + OW_U1, wlo + OW_U1, 512, b_gu1,
        u1, FDIM, FDIM, FDIM, nullptr, nullptr, nullptr, 0, 0.f, nullptr);
    gemm_mma<E_RESID, 0><<<gF, 512, GEMM_DSMEM>>>(u1, FDIM, whi + OW_U2, wlo + OW_U2, 512, b_gu2,
        fused, FDIM, FDIM, FDIM, nullptr, nullptr, base, FDIM, 0.5f, gp);

    gemm_mma<E_BN, 0><<<gA, 512, GEMM_DSMEM>>>(fused, FDIM, whi + OW_CL1, wlo + OW_CL1, 512, b_c1,
        hbuf, HH, HH, FDIM, bn_g, bn_b, nullptr, 0, 0.f, nullptr);
    c2_kernel<<<BB / 8, 256>>>(W_c2, b_c2, out);

    ent_reduce_kernel<<<1, 256>>>(out + (out_size - 1));
}